// round 1
// baseline (speedup 1.0000x reference)
#include <cuda_runtime.h>
#include <cuda_bf16.h>
#include <math.h>

#define B_   8
#define T_   1024
#define C_   1024
#define H_   16
#define DH   64
#define M_   (B_*T_)          // 8192 rows of the activation stream
#define EPS_ 1e-5f

// ---------------- scratch (device globals: allocation-free rule) ----------------
__device__ float g_xn  [M_*C_];                       // LN output (reused for LN2)
__device__ float g_q   [M_*C_];                       // [B,H,T,Dh]
__device__ float g_k   [M_*C_];
__device__ float g_v   [M_*C_];
__device__ float g_s   [(size_t)B_*H_*T_*T_];         // scores / probs, 512MB
__device__ float g_attn[M_*C_];                       // [B,T,C] (heads concat)
__device__ float g_x1  [M_*C_];                       // x + attn proj
__device__ float g_h1  [M_*C_];                       // relu(mlp1)

// ---------------- LayerNorm: one block (256 thr) per row ----------------
__global__ void __launch_bounds__(256) ln_kernel(const float* __restrict__ x,
                                                 const float* __restrict__ g,
                                                 const float* __restrict__ beta,
                                                 float* __restrict__ out)
{
    int row = blockIdx.x;
    int tid = threadIdx.x;
    float4 v = reinterpret_cast<const float4*>(x + (size_t)row * C_)[tid];
    float s  = v.x + v.y + v.z + v.w;
    float ss = v.x*v.x + v.y*v.y + v.z*v.z + v.w*v.w;

    __shared__ float shs[8], shss[8];
    #pragma unroll
    for (int o = 16; o; o >>= 1) {
        s  += __shfl_xor_sync(0xffffffffu, s,  o);
        ss += __shfl_xor_sync(0xffffffffu, ss, o);
    }
    if ((tid & 31) == 0) { shs[tid >> 5] = s; shss[tid >> 5] = ss; }
    __syncthreads();
    if (tid < 32) {
        float s2  = (tid < 8) ? shs[tid]  : 0.f;
        float ss2 = (tid < 8) ? shss[tid] : 0.f;
        #pragma unroll
        for (int o = 4; o; o >>= 1) {
            s2  += __shfl_xor_sync(0xffffffffu, s2,  o);
            ss2 += __shfl_xor_sync(0xffffffffu, ss2, o);
        }
        if (tid == 0) { shs[0] = s2; shss[0] = ss2; }
    }
    __syncthreads();
    float mean = shs[0]  * (1.f / C_);
    float var  = shss[0] * (1.f / C_) - mean * mean;
    float inv  = rsqrtf(var + EPS_);

    float4 gg = reinterpret_cast<const float4*>(g)[tid];
    float4 bb = reinterpret_cast<const float4*>(beta)[tid];
    float4 o4;
    o4.x = gg.x * (v.x - mean) * inv + bb.x;
    o4.y = gg.y * (v.y - mean) * inv + bb.y;
    o4.z = gg.z * (v.z - mean) * inv + bb.z;
    o4.w = gg.w * (v.w - mean) * inv + bb.w;
    reinterpret_cast<float4*>(out + (size_t)row * C_)[tid] = o4;
}

// ---------------- 128x128x8 SGEMM, 256 threads, 8x8 microtile ----------------
enum { EPI_QKV = 0, EPI_PROJ = 1, EPI_RELU = 2, EPI_RESID = 3 };

template<int EPI>
__global__ void __launch_bounds__(256) sgemm_kernel(
    const float* __restrict__ A,     // [M,K] row-major
    const float* __restrict__ W,     // plain [K,N] or qkv [H,C,Dh]
    const float* __restrict__ bias,  // [N] (PROJ/RELU/RESID)
    const float* __restrict__ resid, // [M,N] (PROJ/RESID)
    float*       __restrict__ out,
    int M, int N, int K)
{
    __shared__ float As[8][128];
    __shared__ float Bs[8][128];

    int tid   = threadIdx.x;
    int tx    = tid & 15, ty = tid >> 4;
    int mBase = blockIdx.y * 128, nBase = blockIdx.x * 128;
    int aRow  = tid >> 1, aCol = (tid & 1) * 4;
    int bK    = tid >> 5, bN   = (tid & 31) * 4;

    float acc[8][8];
    #pragma unroll
    for (int i = 0; i < 8; i++)
        #pragma unroll
        for (int j = 0; j < 8; j++) acc[i][j] = 0.f;

    for (int k0 = 0; k0 < K; k0 += 8) {
        float4 av = *reinterpret_cast<const float4*>(
            &A[(size_t)(mBase + aRow) * K + k0 + aCol]);
        As[aCol + 0][aRow] = av.x;
        As[aCol + 1][aRow] = av.y;
        As[aCol + 2][aRow] = av.z;
        As[aCol + 3][aRow] = av.w;

        float4 bv;
        if (EPI == EPI_QKV) {
            int n = nBase + bN;
            int h = n >> 6, d = n & 63;
            bv = *reinterpret_cast<const float4*>(
                &W[(size_t)h * (C_ * DH) + (size_t)(k0 + bK) * DH + d]);
        } else {
            bv = *reinterpret_cast<const float4*>(
                &W[(size_t)(k0 + bK) * N + nBase + bN]);
        }
        *reinterpret_cast<float4*>(&Bs[bK][bN]) = bv;
        __syncthreads();

        #pragma unroll
        for (int kk = 0; kk < 8; kk++) {
            float4 a0 = *reinterpret_cast<float4*>(&As[kk][ty * 8]);
            float4 a1 = *reinterpret_cast<float4*>(&As[kk][ty * 8 + 4]);
            float4 b0 = *reinterpret_cast<float4*>(&Bs[kk][tx * 8]);
            float4 b1 = *reinterpret_cast<float4*>(&Bs[kk][tx * 8 + 4]);
            float a[8] = {a0.x, a0.y, a0.z, a0.w, a1.x, a1.y, a1.z, a1.w};
            float b[8] = {b0.x, b0.y, b0.z, b0.w, b1.x, b1.y, b1.z, b1.w};
            #pragma unroll
            for (int i = 0; i < 8; i++)
                #pragma unroll
                for (int j = 0; j < 8; j++)
                    acc[i][j] = fmaf(a[i], b[j], acc[i][j]);
        }
        __syncthreads();
    }

    #pragma unroll
    for (int i = 0; i < 8; i++) {
        int m = mBase + ty * 8 + i;
        #pragma unroll
        for (int j = 0; j < 8; j++) {
            int n = nBase + tx * 8 + j;
            float val = acc[i][j];
            if (EPI == EPI_QKV) {
                int b = m >> 10, t = m & 1023;     // T_ = 1024
                int h = n >> 6,  d = n & 63;       // DH = 64
                out[((size_t)(b * H_ + h) * T_ + t) * DH + d] = val;
            } else if (EPI == EPI_PROJ || EPI == EPI_RESID) {
                size_t idx = (size_t)m * N + n;
                out[idx] = resid[idx] + val + bias[n];
            } else { // EPI_RELU
                size_t idx = (size_t)m * N + n;
                out[idx] = fmaxf(val + bias[n], 0.f);
            }
        }
    }
}

// ---------------- attention scores: S = Q K^T * Dh^-0.5 (lower-tri blocks only) ---
__global__ void __launch_bounds__(256) scores_kernel()
{
    int kt = blockIdx.x, qt = blockIdx.y, bh = blockIdx.z;
    if (kt > qt) return;                       // causal: never read upstream

    __shared__ float Qs[DH][64];               // [d][m]
    __shared__ float Ks[DH][64];               // [d][n]
    int tid = threadIdx.x;
    int row = tid >> 2, seg = (tid & 3) * 4;
    const float* qp = g_q + ((size_t)bh * T_ + qt * 64 + row) * DH;
    const float* kp = g_k + ((size_t)bh * T_ + kt * 64 + row) * DH;

    #pragma unroll
    for (int ch = 0; ch < 4; ch++) {
        int c = ch * 16 + seg;
        float4 qv = *reinterpret_cast<const float4*>(qp + c);
        Qs[c + 0][row] = qv.x; Qs[c + 1][row] = qv.y;
        Qs[c + 2][row] = qv.z; Qs[c + 3][row] = qv.w;
        float4 kv = *reinterpret_cast<const float4*>(kp + c);
        Ks[c + 0][row] = kv.x; Ks[c + 1][row] = kv.y;
        Ks[c + 2][row] = kv.z; Ks[c + 3][row] = kv.w;
    }
    __syncthreads();

    int tx = tid & 15, ty = tid >> 4;
    float acc[4][4];
    #pragma unroll
    for (int i = 0; i < 4; i++)
        #pragma unroll
        for (int j = 0; j < 4; j++) acc[i][j] = 0.f;

    #pragma unroll 16
    for (int d = 0; d < DH; d++) {
        float4 a = *reinterpret_cast<float4*>(&Qs[d][ty * 4]);
        float4 b = *reinterpret_cast<float4*>(&Ks[d][tx * 4]);
        float av[4] = {a.x, a.y, a.z, a.w};
        float bv[4] = {b.x, b.y, b.z, b.w};
        #pragma unroll
        for (int i = 0; i < 4; i++)
            #pragma unroll
            for (int j = 0; j < 4; j++)
                acc[i][j] = fmaf(av[i], bv[j], acc[i][j]);
    }

    #pragma unroll
    for (int i = 0; i < 4; i++) {
        int t = qt * 64 + ty * 4 + i;
        float4 o;
        o.x = acc[i][0] * 0.125f;  // Dh^-0.5 = 1/8
        o.y = acc[i][1] * 0.125f;
        o.z = acc[i][2] * 0.125f;
        o.w = acc[i][3] * 0.125f;
        *reinterpret_cast<float4*>(
            &g_s[((size_t)bh * T_ + t) * T_ + kt * 64 + tx * 4]) = o;
    }
}

// ---------------- causal softmax over row (in-place on g_s, zeros above diag) ---
__global__ void __launch_bounds__(256) softmax_kernel()
{
    int row = blockIdx.x;           // bh*T + t
    int t   = row & (T_ - 1);
    float* S = g_s + (size_t)row * T_;
    int tid = threadIdx.x;

    float v[4];
    #pragma unroll
    for (int i = 0; i < 4; i++) {
        int s = tid + i * 256;
        v[i] = (s <= t) ? S[s] : -INFINITY;
    }
    float mx = fmaxf(fmaxf(v[0], v[1]), fmaxf(v[2], v[3]));

    __shared__ float shm[8], shsum[8];
    #pragma unroll
    for (int o = 16; o; o >>= 1) mx = fmaxf(mx, __shfl_xor_sync(0xffffffffu, mx, o));
    if ((tid & 31) == 0) shm[tid >> 5] = mx;
    __syncthreads();
    if (tid < 32) {
        float m2 = (tid < 8) ? shm[tid] : -INFINITY;
        #pragma unroll
        for (int o = 4; o; o >>= 1) m2 = fmaxf(m2, __shfl_xor_sync(0xffffffffu, m2, o));
        if (tid == 0) shm[0] = m2;
    }
    __syncthreads();
    mx = shm[0];

    float sum = 0.f;
    #pragma unroll
    for (int i = 0; i < 4; i++) {
        int s = tid + i * 256;
        float e = (s <= t) ? __expf(v[i] - mx) : 0.f;
        v[i] = e;
        sum += e;
    }
    #pragma unroll
    for (int o = 16; o; o >>= 1) sum += __shfl_xor_sync(0xffffffffu, sum, o);
    if ((tid & 31) == 0) shsum[tid >> 5] = sum;
    __syncthreads();
    if (tid < 32) {
        float s2 = (tid < 8) ? shsum[tid] : 0.f;
        #pragma unroll
        for (int o = 4; o; o >>= 1) s2 += __shfl_xor_sync(0xffffffffu, s2, o);
        if (tid == 0) shsum[0] = s2;
    }
    __syncthreads();
    float inv = 1.f / shsum[0];

    #pragma unroll
    for (int i = 0; i < 4; i++)
        S[tid + i * 256] = v[i] * inv;
}

// ---------------- attn = P @ V  (causally clipped K range) ----------------
__global__ void __launch_bounds__(256) pv_kernel()
{
    int qt = blockIdx.x, bh = blockIdx.y;
    __shared__ float Ps[16][64];   // [k][m]
    __shared__ float Vs[16][64];   // [k][n]
    int tid  = threadIdx.x;
    int tx   = tid & 15, ty = tid >> 4;
    int aRow = tid >> 2, aSeg = (tid & 3) * 4;
    int bK   = tid >> 4, bN   = (tid & 15) * 4;

    float acc[4][4];
    #pragma unroll
    for (int i = 0; i < 4; i++)
        #pragma unroll
        for (int j = 0; j < 4; j++) acc[i][j] = 0.f;

    int kmax = (qt + 1) * 64;      // P is zero beyond row's causal extent
    for (int k0 = 0; k0 < kmax; k0 += 16) {
        float4 pv = *reinterpret_cast<const float4*>(
            &g_s[((size_t)bh * T_ + qt * 64 + aRow) * T_ + k0 + aSeg]);
        Ps[aSeg + 0][aRow] = pv.x; Ps[aSeg + 1][aRow] = pv.y;
        Ps[aSeg + 2][aRow] = pv.z; Ps[aSeg + 3][aRow] = pv.w;
        *reinterpret_cast<float4*>(&Vs[bK][bN]) =
            *reinterpret_cast<const float4*>(
                &g_v[((size_t)bh * T_ + k0 + bK) * DH + bN]);
        __syncthreads();

        #pragma unroll
        for (int kk = 0; kk < 16; kk++) {
            float4 a = *reinterpret_cast<float4*>(&Ps[kk][ty * 4]);
            float4 b = *reinterpret_cast<float4*>(&Vs[kk][tx * 4]);
            float av[4] = {a.x, a.y, a.z, a.w};
            float bv[4] = {b.x, b.y, b.z, b.w};
            #pragma unroll
            for (int i = 0; i < 4; i++)
                #pragma unroll
                for (int j = 0; j < 4; j++)
                    acc[i][j] = fmaf(av[i], bv[j], acc[i][j]);
        }
        __syncthreads();
    }

    int b = bh >> 4, h = bh & 15;
    #pragma unroll
    for (int i = 0; i < 4; i++) {
        int t = qt * 64 + ty * 4 + i;
        float4 o = {acc[i][0], acc[i][1], acc[i][2], acc[i][3]};
        *reinterpret_cast<float4*>(
            &g_attn[((size_t)(b * T_ + t)) * C_ + h * DH + tx * 4]) = o;
    }
}

// ---------------- launch ----------------
extern "C" void kernel_launch(void* const* d_in, const int* in_sizes, int n_in,
                              void* d_out, int out_size)
{
    const float* x     = (const float*)d_in[0];
    const float* Wq    = (const float*)d_in[1];
    const float* Wk    = (const float*)d_in[2];
    const float* Wv    = (const float*)d_in[3];
    const float* Wproj = (const float*)d_in[4];
    const float* bproj = (const float*)d_in[5];
    const float* W1    = (const float*)d_in[6];
    const float* b1    = (const float*)d_in[7];
    const float* W2    = (const float*)d_in[8];
    const float* b2    = (const float*)d_in[9];
    const float* g1    = (const float*)d_in[10];
    const float* beta1 = (const float*)d_in[11];
    const float* g2    = (const float*)d_in[12];
    const float* beta2 = (const float*)d_in[13];
    float* out = (float*)d_out;

    float *xn, *q, *k, *v, *attn, *x1, *h1;
    cudaGetSymbolAddress((void**)&xn,   g_xn);
    cudaGetSymbolAddress((void**)&q,    g_q);
    cudaGetSymbolAddress((void**)&k,    g_k);
    cudaGetSymbolAddress((void**)&v,    g_v);
    cudaGetSymbolAddress((void**)&attn, g_attn);
    cudaGetSymbolAddress((void**)&x1,   g_x1);
    cudaGetSymbolAddress((void**)&h1,   g_h1);

    dim3 gemmGrid(C_ / 128, M_ / 128);   // (8, 64)

    // 1. LN1
    ln_kernel<<<M_, 256>>>(x, g1, beta1, xn);
    // 2. Q, K, V projections ([B,H,T,Dh] layout)
    sgemm_kernel<EPI_QKV><<<gemmGrid, 256>>>(xn, Wq, nullptr, nullptr, q, M_, C_, C_);
    sgemm_kernel<EPI_QKV><<<gemmGrid, 256>>>(xn, Wk, nullptr, nullptr, k, M_, C_, C_);
    sgemm_kernel<EPI_QKV><<<gemmGrid, 256>>>(xn, Wv, nullptr, nullptr, v, M_, C_, C_);
    // 3. scores (lower-triangular blocks only)
    scores_kernel<<<dim3(T_ / 64, T_ / 64, B_ * H_), 256>>>();
    // 4. causal softmax (in-place)
    softmax_kernel<<<B_ * H_ * T_, 256>>>();
    // 5. attn = P @ V (heads re-concatenated to [B,T,C])
    pv_kernel<<<dim3(T_ / 64, B_ * H_), 256>>>();
    // 6. x1 = x + attn @ Wproj + bproj
    sgemm_kernel<EPI_PROJ><<<gemmGrid, 256>>>(attn, Wproj, bproj, x, x1, M_, C_, C_);
    // 7. LN2
    ln_kernel<<<M_, 256>>>(x1, g2, beta2, xn);
    // 8. h1 = relu(xn2 @ W1 + b1)
    sgemm_kernel<EPI_RELU><<<gemmGrid, 256>>>(xn, W1, b1, nullptr, h1, M_, C_, C_);
    // 9. out = x1 + h1 @ W2 + b2
    sgemm_kernel<EPI_RESID><<<gemmGrid, 256>>>(h1, W2, b2, x1, out, M_, C_, C_);
}

// round 3
// speedup vs baseline: 2.3442x; 2.3442x over previous
#include <cuda_runtime.h>
#include <cuda_bf16.h>
#include <math.h>
#include <cstdint>

#define B_   8
#define T_   1024
#define C_   1024
#define H_   16
#define DH   64
#define M_   (B_*T_)
#define KDIM 1024
#define EPS_ 1e-5f

// ---------------- scratch (device globals: allocation-free rule) ----------------
__device__ float g_xn  [M_*C_];
__device__ float g_qkv [3ll*M_*C_];                   // q,k,v each [B,H,T,Dh]
__device__ float g_s   [(size_t)B_*H_*T_*T_];         // scores / probs
__device__ float g_attn[M_*C_];
__device__ float g_x1  [M_*C_];
__device__ float g_h1  [M_*C_];
__device__ float g_wqkv[3ll*C_*C_];                   // transposed [N=3072][K=1024]
__device__ float g_wpt [C_*C_];
__device__ float g_w1t [C_*C_];
__device__ float g_w2t [C_*C_];

// ================= helpers =================
__device__ __forceinline__ uint32_t smem_u32(const void* p) {
    uint32_t a;
    asm("{ .reg .u64 t; cvta.to.shared.u64 t, %1; cvt.u32.u64 %0, t; }" : "=r"(a) : "l"(p));
    return a;
}
__device__ __forceinline__ float to_tf32(float x) {
    uint32_t u;
    asm("cvt.rna.tf32.f32 %0, %1;" : "=r"(u) : "f"(x));
    return __uint_as_float(u);
}
__device__ __forceinline__ void cp_async16(uint32_t dst, const void* src) {
    asm volatile("cp.async.cg.shared.global [%0], [%1], 16;" :: "r"(dst), "l"(src));
}
#define CP_COMMIT() asm volatile("cp.async.commit_group;" ::: "memory")
#define CP_WAIT(n)  asm volatile("cp.async.wait_group %0;" :: "n"(n) : "memory")

// m16n8k8 tf32 MMA, fp32 accumulate (family-portable HMMA path)
__device__ __forceinline__ void mma_tf32(float* d, const uint32_t* a, const uint32_t* b) {
    asm volatile(
        "mma.sync.aligned.m16n8k8.row.col.f32.tf32.tf32.f32 "
        "{%0,%1,%2,%3}, {%4,%5,%6,%7}, {%8,%9}, {%0,%1,%2,%3};"
        : "+f"(d[0]), "+f"(d[1]), "+f"(d[2]), "+f"(d[3])
        : "r"(a[0]), "r"(a[1]), "r"(a[2]), "r"(a[3]), "r"(b[0]), "r"(b[1]));
}

// swizzled smem index: tile row m (128 rows x 32 floats), element k
__device__ __forceinline__ int sidx(int m, int k) {
    return m * 32 + ((((k >> 2) ^ m) & 7) << 2) + (k & 3);
}

// ================= weight transposes (fp32 -> tf32-rounded [N][K]) =================
__global__ void __launch_bounds__(256) transpose_kernel(const float* __restrict__ in,
                                                        float* __restrict__ out)
{
    __shared__ float tile[32][33];
    int tx = threadIdx.x, ty = threadIdx.y;
    int n0 = blockIdx.x * 32, k0 = blockIdx.y * 32;
    #pragma unroll
    for (int i = 0; i < 32; i += 8)
        tile[ty + i][tx] = in[(size_t)(k0 + ty + i) * C_ + n0 + tx];
    __syncthreads();
    #pragma unroll
    for (int i = 0; i < 32; i += 8)
        out[(size_t)(n0 + ty + i) * KDIM + k0 + tx] = to_tf32(tile[tx][ty + i]);
}

__global__ void __launch_bounds__(256) transpose_qkv_kernel(const float* __restrict__ in,
                                                            float* __restrict__ out)
{
    __shared__ float tile[32][33];
    int tx = threadIdx.x, ty = threadIdx.y;
    int h = blockIdx.z;
    int d0 = blockIdx.x * 32, c0 = blockIdx.y * 32;
    #pragma unroll
    for (int i = 0; i < 32; i += 8)
        tile[ty + i][tx] = in[(size_t)h * (C_ * DH) + (size_t)(c0 + ty + i) * DH + d0 + tx];
    __syncthreads();
    #pragma unroll
    for (int i = 0; i < 32; i += 8)
        out[(size_t)(h * DH + d0 + ty + i) * KDIM + c0 + tx] = to_tf32(tile[tx][ty + i]);
}

// ================= tf32 mma.sync GEMM =================
// D[M,N] = A[M,1024] @ Bt[N,1024]^T ; tile 128x128, BK=32, 3-stage cp.async
enum { EPI_QKV = 0, EPI_PROJ = 1, EPI_RELU = 2, EPI_RESID = 3 };

#define BK 32
#define NCHUNK (KDIM / BK)
#define STAGE_FLOATS 8192                 // 128x32 A + 128x32 B
#define SMEM_SZ (3 * STAGE_FLOATS * 4)    // 96KB

template<int EPI>
__global__ void __launch_bounds__(256) mma_gemm(
    const float* __restrict__ A,      // [M,1024] (tf32-rounded)
    const float* __restrict__ Bt,     // [Ntot,1024] (tf32-rounded)
    const float* __restrict__ bias,
    const float* __restrict__ resid,
    float*       __restrict__ out)
{
    extern __shared__ float sm[];
    int tid = threadIdx.x, wid = tid >> 5, lane = tid & 31;
    int warpM = wid & 3, warpN = wid >> 2;      // 4 x 2 warp grid
    int qrow = lane >> 2, qc = lane & 3;
    int mBase = blockIdx.y * 128, nBase = blockIdx.x * 128;

    const float* aSrc = A  + (size_t)mBase * KDIM;
    const float* bSrc = Bt + (size_t)nBase * KDIM;

    auto load_stage = [&](int c, int s) {
        float* dstA = sm + s * STAGE_FLOATS;
        float* dstB = dstA + 4096;
        #pragma unroll
        for (int i = 0; i < 4; i++) {
            int id = tid + i * 256;
            int m = id >> 3, j = id & 7;
            int jj = j ^ (m & 7);
            cp_async16(smem_u32(dstA + m * 32 + jj * 4),
                       aSrc + (size_t)m * KDIM + c * BK + j * 4);
            cp_async16(smem_u32(dstB + m * 32 + jj * 4),
                       bSrc + (size_t)m * KDIM + c * BK + j * 4);
        }
    };

    float acc[2][8][4];
    #pragma unroll
    for (int mt = 0; mt < 2; mt++)
        #pragma unroll
        for (int nt = 0; nt < 8; nt++)
            #pragma unroll
            for (int r = 0; r < 4; r++) acc[mt][nt][r] = 0.f;

    load_stage(0, 0); CP_COMMIT();
    load_stage(1, 1); CP_COMMIT();

    #pragma unroll 1
    for (int c = 0; c < NCHUNK; c++) {
        if (c < NCHUNK - 2) { CP_WAIT(1); } else { CP_WAIT(0); }
        __syncthreads();
        if (c + 2 < NCHUNK) { load_stage(c + 2, (c + 2) % 3); CP_COMMIT(); }

        const float* sA = sm + (c % 3) * STAGE_FLOATS;
        const float* sB = sA + 4096;

        #pragma unroll
        for (int ks = 0; ks < 4; ks++) {
            int k0 = ks * 8 + qc;
            uint32_t af[2][4];
            #pragma unroll
            for (int mt = 0; mt < 2; mt++) {
                int m0 = warpM * 32 + mt * 16 + qrow;
                af[mt][0] = __float_as_uint(sA[sidx(m0,     k0)]);
                af[mt][1] = __float_as_uint(sA[sidx(m0 + 8, k0)]);
                af[mt][2] = __float_as_uint(sA[sidx(m0,     k0 + 4)]);
                af[mt][3] = __float_as_uint(sA[sidx(m0 + 8, k0 + 4)]);
            }
            #pragma unroll
            for (int nt = 0; nt < 8; nt++) {
                int n0 = warpN * 64 + nt * 8 + qrow;
                uint32_t bf[2] = { __float_as_uint(sB[sidx(n0, k0)]),
                                   __float_as_uint(sB[sidx(n0, k0 + 4)]) };
                mma_tf32(acc[0][nt], af[0], bf);
                mma_tf32(acc[1][nt], af[1], bf);
            }
        }
    }

    // ---- epilogue ----
    #pragma unroll
    for (int mt = 0; mt < 2; mt++) {
        #pragma unroll
        for (int r = 0; r < 2; r++) {
            int m = mBase + warpM * 32 + mt * 16 + qrow + r * 8;
            #pragma unroll
            for (int nt = 0; nt < 8; nt++) {
                int col = nBase + warpN * 64 + nt * 8 + qc * 2;
                float vx = acc[mt][nt][r * 2], vy = acc[mt][nt][r * 2 + 1];
                if (EPI == EPI_QKV) {
                    int which = col >> 10, nn = col & 1023;
                    int h = nn >> 6, d = nn & 63;
                    int b = m >> 10, t = m & 1023;
                    float2 o = { vx, vy };
                    *reinterpret_cast<float2*>(
                        &out[(size_t)which * (M_ * C_) +
                             (((size_t)(b * H_ + h) * T_ + t) * DH + d)]) = o;
                } else {
                    size_t idx = (size_t)m * C_ + col;
                    float bx = bias[col], by = bias[col + 1];
                    float ox = vx + bx, oy = vy + by;
                    if (EPI == EPI_RELU) {
                        ox = to_tf32(fmaxf(ox, 0.f));    // feeds next GEMM's A
                        oy = to_tf32(fmaxf(oy, 0.f));
                    } else {
                        float2 rs = *reinterpret_cast<const float2*>(&resid[idx]);
                        ox += rs.x; oy += rs.y;
                    }
                    float2 o = { ox, oy };
                    *reinterpret_cast<float2*>(&out[idx]) = o;
                }
            }
        }
    }
}

// ================= LayerNorm (tf32-rounded output: feeds GEMM A) =================
__global__ void __launch_bounds__(256) ln_kernel(const float* __restrict__ x,
                                                 const float* __restrict__ g,
                                                 const float* __restrict__ beta,
                                                 float* __restrict__ out)
{
    int row = blockIdx.x, tid = threadIdx.x;
    float4 v = reinterpret_cast<const float4*>(x + (size_t)row * C_)[tid];
    float s  = v.x + v.y + v.z + v.w;
    float ss = v.x*v.x + v.y*v.y + v.z*v.z + v.w*v.w;
    __shared__ float shs[8], shss[8];
    #pragma unroll
    for (int o = 16; o; o >>= 1) {
        s  += __shfl_xor_sync(0xffffffffu, s,  o);
        ss += __shfl_xor_sync(0xffffffffu, ss, o);
    }
    if ((tid & 31) == 0) { shs[tid >> 5] = s; shss[tid >> 5] = ss; }
    __syncthreads();
    if (tid < 32) {
        float s2  = (tid < 8) ? shs[tid]  : 0.f;
        float ss2 = (tid < 8) ? shss[tid] : 0.f;
        #pragma unroll
        for (int o = 4; o; o >>= 1) {
            s2  += __shfl_xor_sync(0xffffffffu, s2,  o);
            ss2 += __shfl_xor_sync(0xffffffffu, ss2, o);
        }
        if (tid == 0) { shs[0] = s2; shss[0] = ss2; }
    }
    __syncthreads();
    float mean = shs[0] * (1.f / C_);
    float var  = shss[0] * (1.f / C_) - mean * mean;
    float inv  = rsqrtf(var + EPS_);
    float4 gg = reinterpret_cast<const float4*>(g)[tid];
    float4 bb = reinterpret_cast<const float4*>(beta)[tid];
    float4 o4 = { to_tf32(gg.x * (v.x - mean) * inv + bb.x),
                  to_tf32(gg.y * (v.y - mean) * inv + bb.y),
                  to_tf32(gg.z * (v.z - mean) * inv + bb.z),
                  to_tf32(gg.w * (v.w - mean) * inv + bb.w) };
    reinterpret_cast<float4*>(out + (size_t)row * C_)[tid] = o4;
}

// ================= attention (fp32, unchanged this round) =================
__global__ void __launch_bounds__(256) scores_kernel()
{
    int kt = blockIdx.x, qt = blockIdx.y, bh = blockIdx.z;
    if (kt > qt) return;
    const float* gq = g_qkv;
    const float* gk = g_qkv + (size_t)M_ * C_;
    __shared__ float Qs[DH][64];
    __shared__ float Ks[DH][64];
    int tid = threadIdx.x;
    int row = tid >> 2, seg = (tid & 3) * 4;
    const float* qp = gq + ((size_t)bh * T_ + qt * 64 + row) * DH;
    const float* kp = gk + ((size_t)bh * T_ + kt * 64 + row) * DH;
    #pragma unroll
    for (int ch = 0; ch < 4; ch++) {
        int c = ch * 16 + seg;
        float4 qv = *reinterpret_cast<const float4*>(qp + c);
        Qs[c+0][row] = qv.x; Qs[c+1][row] = qv.y; Qs[c+2][row] = qv.z; Qs[c+3][row] = qv.w;
        float4 kv = *reinterpret_cast<const float4*>(kp + c);
        Ks[c+0][row] = kv.x; Ks[c+1][row] = kv.y; Ks[c+2][row] = kv.z; Ks[c+3][row] = kv.w;
    }
    __syncthreads();
    int tx = tid & 15, ty = tid >> 4;
    float acc[4][4];
    #pragma unroll
    for (int i = 0; i < 4; i++)
        #pragma unroll
        for (int j = 0; j < 4; j++) acc[i][j] = 0.f;
    #pragma unroll 16
    for (int d = 0; d < DH; d++) {
        float4 a = *reinterpret_cast<float4*>(&Qs[d][ty * 4]);
        float4 b = *reinterpret_cast<float4*>(&Ks[d][tx * 4]);
        float av[4] = {a.x, a.y, a.z, a.w};
        float bv[4] = {b.x, b.y, b.z, b.w};
        #pragma unroll
        for (int i = 0; i < 4; i++)
            #pragma unroll
            for (int j = 0; j < 4; j++)
                acc[i][j] = fmaf(av[i], bv[j], acc[i][j]);
    }
    #pragma unroll
    for (int i = 0; i < 4; i++) {
        int t = qt * 64 + ty * 4 + i;
        float4 o = { acc[i][0]*0.125f, acc[i][1]*0.125f, acc[i][2]*0.125f, acc[i][3]*0.125f };
        *reinterpret_cast<float4*>(&g_s[((size_t)bh * T_ + t) * T_ + kt * 64 + tx * 4]) = o;
    }
}

__global__ void __launch_bounds__(256) softmax_kernel()
{
    int row = blockIdx.x;
    int t   = row & (T_ - 1);
    float* S = g_s + (size_t)row * T_;
    int tid = threadIdx.x;
    float v[4];
    #pragma unroll
    for (int i = 0; i < 4; i++) {
        int s = tid + i * 256;
        v[i] = (s <= t) ? S[s] : -INFINITY;
    }
    float mx = fmaxf(fmaxf(v[0], v[1]), fmaxf(v[2], v[3]));
    __shared__ float shm[8], shsum[8];
    #pragma unroll
    for (int o = 16; o; o >>= 1) mx = fmaxf(mx, __shfl_xor_sync(0xffffffffu, mx, o));
    if ((tid & 31) == 0) shm[tid >> 5] = mx;
    __syncthreads();
    if (tid < 32) {
        float m2 = (tid < 8) ? shm[tid] : -INFINITY;
        #pragma unroll
        for (int o = 4; o; o >>= 1) m2 = fmaxf(m2, __shfl_xor_sync(0xffffffffu, m2, o));
        if (tid == 0) shm[0] = m2;
    }
    __syncthreads();
    mx = shm[0];
    float sum = 0.f;
    #pragma unroll
    for (int i = 0; i < 4; i++) {
        int s = tid + i * 256;
        float e = (s <= t) ? __expf(v[i] - mx) : 0.f;
        v[i] = e; sum += e;
    }
    #pragma unroll
    for (int o = 16; o; o >>= 1) sum += __shfl_xor_sync(0xffffffffu, sum, o);
    if ((tid & 31) == 0) shsum[tid >> 5] = sum;
    __syncthreads();
    if (tid < 32) {
        float s2 = (tid < 8) ? shsum[tid] : 0.f;
        #pragma unroll
        for (int o = 4; o; o >>= 1) s2 += __shfl_xor_sync(0xffffffffu, s2, o);
        if (tid == 0) shsum[0] = s2;
    }
    __syncthreads();
    float inv = 1.f / shsum[0];
    #pragma unroll
    for (int i = 0; i < 4; i++)
        S[tid + i * 256] = v[i] * inv;
}

__global__ void __launch_bounds__(256) pv_kernel()
{
    int qt = blockIdx.x, bh = blockIdx.y;
    const float* gv = g_qkv + 2ll * M_ * C_;
    __shared__ float Ps[16][64];
    __shared__ float Vs[16][64];
    int tid  = threadIdx.x;
    int tx   = tid & 15, ty = tid >> 4;
    int aRow = tid >> 2, aSeg = (tid & 3) * 4;
    int bK   = tid >> 4, bN   = (tid & 15) * 4;
    float acc[4][4];
    #pragma unroll
    for (int i = 0; i < 4; i++)
        #pragma unroll
        for (int j = 0; j < 4; j++) acc[i][j] = 0.f;
    int kmax = (qt + 1) * 64;
    for (int k0 = 0; k0 < kmax; k0 += 16) {
        float4 pv = *reinterpret_cast<const float4*>(
            &g_s[((size_t)bh * T_ + qt * 64 + aRow) * T_ + k0 + aSeg]);
        Ps[aSeg+0][aRow] = pv.x; Ps[aSeg+1][aRow] = pv.y;
        Ps[aSeg+2][aRow] = pv.z; Ps[aSeg+3][aRow] = pv.w;
        *reinterpret_cast<float4*>(&Vs[bK][bN]) =
            *reinterpret_cast<const float4*>(&gv[((size_t)bh * T_ + k0 + bK) * DH + bN]);
        __syncthreads();
        #pragma unroll
        for (int kk = 0; kk < 16; kk++) {
            float4 a = *reinterpret_cast<float4*>(&Ps[kk][ty * 4]);
            float4 b = *reinterpret_cast<float4*>(&Vs[kk][tx * 4]);
            float av[4] = {a.x, a.y, a.z, a.w};
            float bv[4] = {b.x, b.y, b.z, b.w};
            #pragma unroll
            for (int i = 0; i < 4; i++)
                #pragma unroll
                for (int j = 0; j < 4; j++)
                    acc[i][j] = fmaf(av[i], bv[j], acc[i][j]);
        }
        __syncthreads();
    }
    int b = bh >> 4, h = bh & 15;
    #pragma unroll
    for (int i = 0; i < 4; i++) {
        int t = qt * 64 + ty * 4 + i;
        // tf32-round: attn feeds the proj GEMM's A operand
        float4 o = { to_tf32(acc[i][0]), to_tf32(acc[i][1]),
                     to_tf32(acc[i][2]), to_tf32(acc[i][3]) };
        *reinterpret_cast<float4*>(&g_attn[((size_t)(b * T_ + t)) * C_ + h * DH + tx * 4]) = o;
    }
}

// ================= launch =================
extern "C" void kernel_launch(void* const* d_in, const int* in_sizes, int n_in,
                              void* d_out, int out_size)
{
    const float* x     = (const float*)d_in[0];
    const float* Wq    = (const float*)d_in[1];
    const float* Wk    = (const float*)d_in[2];
    const float* Wv    = (const float*)d_in[3];
    const float* Wproj = (const float*)d_in[4];
    const float* bproj = (const float*)d_in[5];
    const float* W1    = (const float*)d_in[6];
    const float* b1    = (const float*)d_in[7];
    const float* W2    = (const float*)d_in[8];
    const float* b2    = (const float*)d_in[9];
    const float* g1    = (const float*)d_in[10];
    const float* beta1 = (const float*)d_in[11];
    const float* g2    = (const float*)d_in[12];
    const float* beta2 = (const float*)d_in[13];
    float* out = (float*)d_out;

    float *xn, *qkv, *attn, *x1, *h1, *wqkv, *wpt, *w1t, *w2t;
    cudaGetSymbolAddress((void**)&xn,   g_xn);
    cudaGetSymbolAddress((void**)&qkv,  g_qkv);
    cudaGetSymbolAddress((void**)&attn, g_attn);
    cudaGetSymbolAddress((void**)&x1,   g_x1);
    cudaGetSymbolAddress((void**)&h1,   g_h1);
    cudaGetSymbolAddress((void**)&wqkv, g_wqkv);
    cudaGetSymbolAddress((void**)&wpt,  g_wpt);
    cudaGetSymbolAddress((void**)&w1t,  g_w1t);
    cudaGetSymbolAddress((void**)&w2t,  g_w2t);

    cudaFuncSetAttribute(mma_gemm<EPI_QKV>,   cudaFuncAttributeMaxDynamicSharedMemorySize, SMEM_SZ);
    cudaFuncSetAttribute(mma_gemm<EPI_PROJ>,  cudaFuncAttributeMaxDynamicSharedMemorySize, SMEM_SZ);
    cudaFuncSetAttribute(mma_gemm<EPI_RELU>,  cudaFuncAttributeMaxDynamicSharedMemorySize, SMEM_SZ);
    cudaFuncSetAttribute(mma_gemm<EPI_RESID>, cudaFuncAttributeMaxDynamicSharedMemorySize, SMEM_SZ);

    dim3 tp(32, 8);
    // weight transposes + tf32 rounding (every launch; deterministic)
    transpose_qkv_kernel<<<dim3(2, 32, 16), tp>>>(Wq, wqkv);
    transpose_qkv_kernel<<<dim3(2, 32, 16), tp>>>(Wk, wqkv + (size_t)C_ * C_);
    transpose_qkv_kernel<<<dim3(2, 32, 16), tp>>>(Wv, wqkv + 2ll * C_ * C_);
    transpose_kernel<<<dim3(32, 32), tp>>>(Wproj, wpt);
    transpose_kernel<<<dim3(32, 32), tp>>>(W1, w1t);
    transpose_kernel<<<dim3(32, 32), tp>>>(W2, w2t);

    // 1. LN1
    ln_kernel<<<M_, 256>>>(x, g1, beta1, xn);
    // 2. fused QKV (N = 3072)
    mma_gemm<EPI_QKV><<<dim3(3 * C_ / 128, M_ / 128), 256, SMEM_SZ>>>(xn, wqkv, nullptr, nullptr, qkv);
    // 3. scores (lower-tri blocks only)
    scores_kernel<<<dim3(T_ / 64, T_ / 64, B_ * H_), 256>>>();
    // 4. causal softmax
    softmax_kernel<<<B_ * H_ * T_, 256>>>();
    // 5. attn = P @ V
    pv_kernel<<<dim3(T_ / 64, B_ * H_), 256>>>();
    // 6. x1 = x + attn @ Wproj + bproj
    mma_gemm<EPI_PROJ><<<dim3(C_ / 128, M_ / 128), 256, SMEM_SZ>>>(attn, wpt, bproj, x, x1);
    // 7. LN2
    ln_kernel<<<M_, 256>>>(x1, g2, beta2, xn);
    // 8. h1 = relu(xn @ W1 + b1)
    mma_gemm<EPI_RELU><<<dim3(C_ / 128, M_ / 128), 256, SMEM_SZ>>>(xn, w1t, b1, nullptr, h1);
    // 9. out = x1 + h1 @ W2 + b2
    mma_gemm<EPI_RESID><<<dim3(C_ / 128, M_ / 128), 256, SMEM_SZ>>>(h1, w2t, b2, x1, out);
}

// round 4
// speedup vs baseline: 3.6367x; 1.5513x over previous
#include <cuda_runtime.h>
#include <cuda_bf16.h>
#include <math.h>
#include <cstdint>

#define B_   8
#define T_   1024
#define C_   1024
#define H_   16
#define DH   64
#define M_   (B_*T_)
#define KDIM 1024
#define EPS_ 1e-5f

// ---------------- scratch (device globals: allocation-free rule) ----------------
__device__ float g_xn  [M_*C_];
__device__ float g_qkv [3ll*M_*C_];                   // q,k,v each [B,H,T,Dh] (tf32, q pre-scaled)
__device__ float g_attn[M_*C_];                       // [B,T,C] tf32
__device__ float g_x1  [M_*C_];
__device__ float g_h1  [M_*C_];
__device__ float g_wqkv[3ll*C_*C_];                   // transposed [N=3072][K=1024] tf32
__device__ float g_wpt [C_*C_];
__device__ float g_w1t [C_*C_];
__device__ float g_w2t [C_*C_];

// ================= helpers =================
__device__ __forceinline__ uint32_t smem_u32(const void* p) {
    uint32_t a;
    asm("{ .reg .u64 t; cvta.to.shared.u64 t, %1; cvt.u32.u64 %0, t; }" : "=r"(a) : "l"(p));
    return a;
}
__device__ __forceinline__ float to_tf32(float x) {
    uint32_t u;
    asm("cvt.rna.tf32.f32 %0, %1;" : "=r"(u) : "f"(x));
    return __uint_as_float(u);
}
__device__ __forceinline__ void cp_async16(uint32_t dst, const void* src) {
    asm volatile("cp.async.cg.shared.global [%0], [%1], 16;" :: "r"(dst), "l"(src));
}
#define CP_COMMIT() asm volatile("cp.async.commit_group;" ::: "memory")
#define CP_WAIT(n)  asm volatile("cp.async.wait_group %0;" :: "n"(n) : "memory")

// m16n8k8 tf32 MMA, fp32 accumulate
__device__ __forceinline__ void mma_tf32(float* d, const uint32_t* a, const uint32_t* b) {
    asm volatile(
        "mma.sync.aligned.m16n8k8.row.col.f32.tf32.tf32.f32 "
        "{%0,%1,%2,%3}, {%4,%5,%6,%7}, {%8,%9}, {%0,%1,%2,%3};"
        : "+f"(d[0]), "+f"(d[1]), "+f"(d[2]), "+f"(d[3])
        : "r"(a[0]), "r"(a[1]), "r"(a[2]), "r"(a[3]), "r"(b[0]), "r"(b[1]));
}

// swizzled smem index for GEMM tiles: row m (x32 floats), element k
__device__ __forceinline__ int sidx(int m, int k) {
    return m * 32 + ((((k >> 2) ^ m) & 7) << 2) + (k & 3);
}

// ================= weight transposes (fp32 -> tf32-rounded [N][K]) =================
__global__ void __launch_bounds__(256) transpose_kernel(const float* __restrict__ in,
                                                        float* __restrict__ out)
{
    __shared__ float tile[32][33];
    int tx = threadIdx.x, ty = threadIdx.y;
    int n0 = blockIdx.x * 32, k0 = blockIdx.y * 32;
    #pragma unroll
    for (int i = 0; i < 32; i += 8)
        tile[ty + i][tx] = in[(size_t)(k0 + ty + i) * C_ + n0 + tx];
    __syncthreads();
    #pragma unroll
    for (int i = 0; i < 32; i += 8)
        out[(size_t)(n0 + ty + i) * KDIM + k0 + tx] = to_tf32(tile[tx][ty + i]);
}

__global__ void __launch_bounds__(256) transpose_qkv_kernel(const float* __restrict__ in,
                                                            float* __restrict__ out)
{
    __shared__ float tile[32][33];
    int tx = threadIdx.x, ty = threadIdx.y;
    int h = blockIdx.z;
    int d0 = blockIdx.x * 32, c0 = blockIdx.y * 32;
    #pragma unroll
    for (int i = 0; i < 32; i += 8)
        tile[ty + i][tx] = in[(size_t)h * (C_ * DH) + (size_t)(c0 + ty + i) * DH + d0 + tx];
    __syncthreads();
    #pragma unroll
    for (int i = 0; i < 32; i += 8)
        out[(size_t)(h * DH + d0 + ty + i) * KDIM + c0 + tx] = to_tf32(tile[tx][ty + i]);
}

// ================= tf32 mma.sync GEMM (128x128, BK=32, 3-stage) =================
enum { EPI_QKV = 0, EPI_PROJ = 1, EPI_RELU = 2, EPI_RESID = 3 };

#define BK 32
#define NCHUNK (KDIM / BK)
#define STAGE_FLOATS 8192
#define SMEM_SZ (3 * STAGE_FLOATS * 4)

template<int EPI>
__global__ void __launch_bounds__(256) mma_gemm(
    const float* __restrict__ A,
    const float* __restrict__ Bt,
    const float* __restrict__ bias,
    const float* __restrict__ resid,
    float*       __restrict__ out)
{
    extern __shared__ float sm[];
    int tid = threadIdx.x, wid = tid >> 5, lane = tid & 31;
    int warpM = wid & 3, warpN = wid >> 2;
    int qrow = lane >> 2, qc = lane & 3;
    int mBase = blockIdx.y * 128, nBase = blockIdx.x * 128;

    const float* aSrc = A  + (size_t)mBase * KDIM;
    const float* bSrc = Bt + (size_t)nBase * KDIM;

    auto load_stage = [&](int c, int s) {
        float* dstA = sm + s * STAGE_FLOATS;
        float* dstB = dstA + 4096;
        #pragma unroll
        for (int i = 0; i < 4; i++) {
            int id = tid + i * 256;
            int m = id >> 3, j = id & 7;
            int jj = j ^ (m & 7);
            cp_async16(smem_u32(dstA + m * 32 + jj * 4),
                       aSrc + (size_t)m * KDIM + c * BK + j * 4);
            cp_async16(smem_u32(dstB + m * 32 + jj * 4),
                       bSrc + (size_t)m * KDIM + c * BK + j * 4);
        }
    };

    float acc[2][8][4];
    #pragma unroll
    for (int mt = 0; mt < 2; mt++)
        #pragma unroll
        for (int nt = 0; nt < 8; nt++)
            #pragma unroll
            for (int r = 0; r < 4; r++) acc[mt][nt][r] = 0.f;

    load_stage(0, 0); CP_COMMIT();
    load_stage(1, 1); CP_COMMIT();

    #pragma unroll 1
    for (int c = 0; c < NCHUNK; c++) {
        if (c < NCHUNK - 2) { CP_WAIT(1); } else { CP_WAIT(0); }
        __syncthreads();
        if (c + 2 < NCHUNK) { load_stage(c + 2, (c + 2) % 3); CP_COMMIT(); }

        const float* sA = sm + (c % 3) * STAGE_FLOATS;
        const float* sB = sA + 4096;

        #pragma unroll
        for (int ks = 0; ks < 4; ks++) {
            int k0 = ks * 8 + qc;
            uint32_t af[2][4];
            #pragma unroll
            for (int mt = 0; mt < 2; mt++) {
                int m0 = warpM * 32 + mt * 16 + qrow;
                af[mt][0] = __float_as_uint(sA[sidx(m0,     k0)]);
                af[mt][1] = __float_as_uint(sA[sidx(m0 + 8, k0)]);
                af[mt][2] = __float_as_uint(sA[sidx(m0,     k0 + 4)]);
                af[mt][3] = __float_as_uint(sA[sidx(m0 + 8, k0 + 4)]);
            }
            #pragma unroll
            for (int nt = 0; nt < 8; nt++) {
                int n0 = warpN * 64 + nt * 8 + qrow;
                uint32_t bf[2] = { __float_as_uint(sB[sidx(n0, k0)]),
                                   __float_as_uint(sB[sidx(n0, k0 + 4)]) };
                mma_tf32(acc[0][nt], af[0], bf);
                mma_tf32(acc[1][nt], af[1], bf);
            }
        }
    }

    // ---- epilogue ----
    #pragma unroll
    for (int mt = 0; mt < 2; mt++) {
        #pragma unroll
        for (int r = 0; r < 2; r++) {
            int m = mBase + warpM * 32 + mt * 16 + qrow + r * 8;
            #pragma unroll
            for (int nt = 0; nt < 8; nt++) {
                int col = nBase + warpN * 64 + nt * 8 + qc * 2;
                float vx = acc[mt][nt][r * 2], vy = acc[mt][nt][r * 2 + 1];
                if (EPI == EPI_QKV) {
                    int which = col >> 10, nn = col & 1023;
                    int h = nn >> 6, d = nn & 63;
                    int b = m >> 10, t = m & 1023;
                    // q pre-scaled by Dh^-0.5; all tf32-rounded (feed flash mma)
                    float sc = (which == 0) ? 0.125f : 1.f;
                    float2 o = { to_tf32(vx * sc), to_tf32(vy * sc) };
                    *reinterpret_cast<float2*>(
                        &out[(size_t)which * (M_ * C_) +
                             (((size_t)(b * H_ + h) * T_ + t) * DH + d)]) = o;
                } else {
                    size_t idx = (size_t)m * C_ + col;
                    float bx = bias[col], by = bias[col + 1];
                    float ox = vx + bx, oy = vy + by;
                    if (EPI == EPI_RELU) {
                        ox = to_tf32(fmaxf(ox, 0.f));
                        oy = to_tf32(fmaxf(oy, 0.f));
                    } else {
                        float2 rs = *reinterpret_cast<const float2*>(&resid[idx]);
                        ox += rs.x; oy += rs.y;
                    }
                    float2 o = { ox, oy };
                    *reinterpret_cast<float2*>(&out[idx]) = o;
                }
            }
        }
    }
}

// ================= fused flash attention (tf32 mma, online softmax) =================
// grid (8, 128): x = qt (reversed for balance), y = bh. 256 threads, 8 warps x 16 rows.
#define QS_STRIDE 68
#define PS_STRIDE 132
#define FA_Q 0
#define FA_K 8704
#define FA_V 17408
#define FA_P 26112
#define FA_SMEM ((26112 + 16896) * 4)      // 172032 bytes

__global__ void __launch_bounds__(256) flash_kernel()
{
    extern __shared__ float fs[];
    int tid = threadIdx.x, wid = tid >> 5, lane = tid & 31;
    int qrow = lane >> 2, qc = lane & 3;
    int qt = gridDim.x - 1 - blockIdx.x;      // long CTAs first
    int bh = blockIdx.y;

    const float* Q = g_qkv + ((size_t)bh * T_ + qt * 128) * DH;
    const float* K = g_qkv + (size_t)M_ * C_  + (size_t)bh * T_ * DH;
    const float* V = g_qkv + 2ll * M_ * C_    + (size_t)bh * T_ * DH;

    auto ldtile = [&](float* dst, const float* src) {
        #pragma unroll
        for (int i = 0; i < 8; i++) {
            int id = tid + i * 256;
            int row = id >> 4, c4 = id & 15;
            cp_async16(smem_u32(dst + row * QS_STRIDE + c4 * 4), src + row * 64 + c4 * 4);
        }
    };

    ldtile(fs + FA_Q, Q);
    CP_COMMIT();

    int rowA = wid * 16 + qrow;               // local rows rowA, rowA+8
    float m[2] = { -1e30f, -1e30f }, l[2] = { 0.f, 0.f };
    float o[8][4];
    #pragma unroll
    for (int nt = 0; nt < 8; nt++)
        #pragma unroll
        for (int r = 0; r < 4; r++) o[nt][r] = 0.f;

    float* Ps = fs + FA_P;

    #pragma unroll 1
    for (int kt = 0; kt <= qt; kt++) {
        ldtile(fs + FA_K, K + (size_t)kt * 128 * 64);
        ldtile(fs + FA_V, V + (size_t)kt * 128 * 64);
        CP_COMMIT();
        CP_WAIT(0);
        __syncthreads();

        // ---- S = Q K^T (Q pre-scaled) : per warp 16 rows x 128 cols ----
        float s[16][4];
        #pragma unroll
        for (int nt = 0; nt < 16; nt++)
            #pragma unroll
            for (int r = 0; r < 4; r++) s[nt][r] = 0.f;

        #pragma unroll
        for (int ks = 0; ks < 8; ks++) {
            int k0 = ks * 8 + qc;
            uint32_t af[4] = {
                __float_as_uint(fs[FA_Q + rowA * QS_STRIDE + k0]),
                __float_as_uint(fs[FA_Q + (rowA + 8) * QS_STRIDE + k0]),
                __float_as_uint(fs[FA_Q + rowA * QS_STRIDE + k0 + 4]),
                __float_as_uint(fs[FA_Q + (rowA + 8) * QS_STRIDE + k0 + 4]) };
            #pragma unroll
            for (int nt = 0; nt < 16; nt++) {
                int n0 = nt * 8 + qrow;
                uint32_t bf[2] = {
                    __float_as_uint(fs[FA_K + n0 * QS_STRIDE + k0]),
                    __float_as_uint(fs[FA_K + n0 * QS_STRIDE + k0 + 4]) };
                mma_tf32(s[nt], af, bf);
            }
        }

        // ---- causal mask (diagonal tile only) ----
        if (kt == qt) {
            int r0 = rowA, r1 = rowA + 8;     // local row == global row offset in tile
            #pragma unroll
            for (int nt = 0; nt < 16; nt++) {
                #pragma unroll
                for (int e = 0; e < 2; e++) {
                    int col = nt * 8 + 2 * qc + e;
                    if (col > r0) s[nt][e]     = -1e30f;
                    if (col > r1) s[nt][2 + e] = -1e30f;
                }
            }
        }

        // ---- online softmax ----
        float tm0 = -1e30f, tm1 = -1e30f;
        #pragma unroll
        for (int nt = 0; nt < 16; nt++) {
            tm0 = fmaxf(tm0, fmaxf(s[nt][0], s[nt][1]));
            tm1 = fmaxf(tm1, fmaxf(s[nt][2], s[nt][3]));
        }
        tm0 = fmaxf(tm0, __shfl_xor_sync(0xffffffffu, tm0, 1));
        tm0 = fmaxf(tm0, __shfl_xor_sync(0xffffffffu, tm0, 2));
        tm1 = fmaxf(tm1, __shfl_xor_sync(0xffffffffu, tm1, 1));
        tm1 = fmaxf(tm1, __shfl_xor_sync(0xffffffffu, tm1, 2));

        float mn0 = fmaxf(m[0], tm0), mn1 = fmaxf(m[1], tm1);
        float c0 = __expf(m[0] - mn0), c1 = __expf(m[1] - mn1);
        m[0] = mn0; m[1] = mn1;

        float sum0 = 0.f, sum1 = 0.f;
        #pragma unroll
        for (int nt = 0; nt < 16; nt++) {
            float p0 = __expf(s[nt][0] - mn0);
            float p1 = __expf(s[nt][1] - mn0);
            float p2 = __expf(s[nt][2] - mn1);
            float p3 = __expf(s[nt][3] - mn1);
            sum0 += p0 + p1; sum1 += p2 + p3;
            float2 w0 = { to_tf32(p0), to_tf32(p1) };
            float2 w1 = { to_tf32(p2), to_tf32(p3) };
            *reinterpret_cast<float2*>(&Ps[rowA * PS_STRIDE + nt * 8 + 2 * qc]) = w0;
            *reinterpret_cast<float2*>(&Ps[(rowA + 8) * PS_STRIDE + nt * 8 + 2 * qc]) = w1;
        }
        sum0 += __shfl_xor_sync(0xffffffffu, sum0, 1);
        sum0 += __shfl_xor_sync(0xffffffffu, sum0, 2);
        sum1 += __shfl_xor_sync(0xffffffffu, sum1, 1);
        sum1 += __shfl_xor_sync(0xffffffffu, sum1, 2);
        l[0] = l[0] * c0 + sum0;
        l[1] = l[1] * c1 + sum1;

        #pragma unroll
        for (int nt = 0; nt < 8; nt++) {
            o[nt][0] *= c0; o[nt][1] *= c0;
            o[nt][2] *= c1; o[nt][3] *= c1;
        }
        __syncwarp();                          // P visible warp-wide (warp-local region)

        // ---- O += P @ V ----
        #pragma unroll
        for (int ks = 0; ks < 16; ks++) {
            int k0 = ks * 8 + qc;
            uint32_t af[4] = {
                __float_as_uint(Ps[rowA * PS_STRIDE + k0]),
                __float_as_uint(Ps[(rowA + 8) * PS_STRIDE + k0]),
                __float_as_uint(Ps[rowA * PS_STRIDE + k0 + 4]),
                __float_as_uint(Ps[(rowA + 8) * PS_STRIDE + k0 + 4]) };
            #pragma unroll
            for (int nt = 0; nt < 8; nt++) {
                int n0 = nt * 8 + qrow;
                uint32_t bf[2] = {
                    __float_as_uint(fs[FA_V + k0 * QS_STRIDE + n0]),
                    __float_as_uint(fs[FA_V + (k0 + 4) * QS_STRIDE + n0]) };
                mma_tf32(o[nt], af, bf);
            }
        }
        __syncthreads();                       // protect K/V before next tile's cp.async
    }

    // ---- epilogue: O /= l, tf32-round (feeds proj GEMM), write [B,T,C] ----
    int b = bh >> 4, h = bh & 15;
    int t0 = qt * 128 + rowA;
    float inv0 = 1.f / l[0], inv1 = 1.f / l[1];
    #pragma unroll
    for (int nt = 0; nt < 8; nt++) {
        int col = h * 64 + nt * 8 + 2 * qc;
        float2 o0 = { to_tf32(o[nt][0] * inv0), to_tf32(o[nt][1] * inv0) };
        float2 o1 = { to_tf32(o[nt][2] * inv1), to_tf32(o[nt][3] * inv1) };
        *reinterpret_cast<float2*>(&g_attn[((size_t)(b * T_ + t0)) * C_ + col])     = o0;
        *reinterpret_cast<float2*>(&g_attn[((size_t)(b * T_ + t0 + 8)) * C_ + col]) = o1;
    }
}

// ================= LayerNorm (tf32-rounded output) =================
__global__ void __launch_bounds__(256) ln_kernel(const float* __restrict__ x,
                                                 const float* __restrict__ g,
                                                 const float* __restrict__ beta,
                                                 float* __restrict__ out)
{
    int row = blockIdx.x, tid = threadIdx.x;
    float4 v = reinterpret_cast<const float4*>(x + (size_t)row * C_)[tid];
    float s  = v.x + v.y + v.z + v.w;
    float ss = v.x*v.x + v.y*v.y + v.z*v.z + v.w*v.w;
    __shared__ float shs[8], shss[8];
    #pragma unroll
    for (int o = 16; o; o >>= 1) {
        s  += __shfl_xor_sync(0xffffffffu, s,  o);
        ss += __shfl_xor_sync(0xffffffffu, ss, o);
    }
    if ((tid & 31) == 0) { shs[tid >> 5] = s; shss[tid >> 5] = ss; }
    __syncthreads();
    if (tid < 32) {
        float s2  = (tid < 8) ? shs[tid]  : 0.f;
        float ss2 = (tid < 8) ? shss[tid] : 0.f;
        #pragma unroll
        for (int o = 4; o; o >>= 1) {
            s2  += __shfl_xor_sync(0xffffffffu, s2,  o);
            ss2 += __shfl_xor_sync(0xffffffffu, ss2, o);
        }
        if (tid == 0) { shs[0] = s2; shss[0] = ss2; }
    }
    __syncthreads();
    float mean = shs[0] * (1.f / C_);
    float var  = shss[0] * (1.f / C_) - mean * mean;
    float inv  = rsqrtf(var + EPS_);
    float4 gg = reinterpret_cast<const float4*>(g)[tid];
    float4 bb = reinterpret_cast<const float4*>(beta)[tid];
    float4 o4 = { to_tf32(gg.x * (v.x - mean) * inv + bb.x),
                  to_tf32(gg.y * (v.y - mean) * inv + bb.y),
                  to_tf32(gg.z * (v.z - mean) * inv + bb.z),
                  to_tf32(gg.w * (v.w - mean) * inv + bb.w) };
    reinterpret_cast<float4*>(out + (size_t)row * C_)[tid] = o4;
}

// ================= launch =================
extern "C" void kernel_launch(void* const* d_in, const int* in_sizes, int n_in,
                              void* d_out, int out_size)
{
    const float* x     = (const float*)d_in[0];
    const float* Wq    = (const float*)d_in[1];
    const float* Wk    = (const float*)d_in[2];
    const float* Wv    = (const float*)d_in[3];
    const float* Wproj = (const float*)d_in[4];
    const float* bproj = (const float*)d_in[5];
    const float* W1    = (const float*)d_in[6];
    const float* b1    = (const float*)d_in[7];
    const float* W2    = (const float*)d_in[8];
    const float* b2    = (const float*)d_in[9];
    const float* g1    = (const float*)d_in[10];
    const float* beta1 = (const float*)d_in[11];
    const float* g2    = (const float*)d_in[12];
    const float* beta2 = (const float*)d_in[13];
    float* out = (float*)d_out;

    float *xn, *qkv, *attn, *x1, *h1, *wqkv, *wpt, *w1t, *w2t;
    cudaGetSymbolAddress((void**)&xn,   g_xn);
    cudaGetSymbolAddress((void**)&qkv,  g_qkv);
    cudaGetSymbolAddress((void**)&attn, g_attn);
    cudaGetSymbolAddress((void**)&x1,   g_x1);
    cudaGetSymbolAddress((void**)&h1,   g_h1);
    cudaGetSymbolAddress((void**)&wqkv, g_wqkv);
    cudaGetSymbolAddress((void**)&wpt,  g_wpt);
    cudaGetSymbolAddress((void**)&w1t,  g_w1t);
    cudaGetSymbolAddress((void**)&w2t,  g_w2t);

    cudaFuncSetAttribute(mma_gemm<EPI_QKV>,   cudaFuncAttributeMaxDynamicSharedMemorySize, SMEM_SZ);
    cudaFuncSetAttribute(mma_gemm<EPI_PROJ>,  cudaFuncAttributeMaxDynamicSharedMemorySize, SMEM_SZ);
    cudaFuncSetAttribute(mma_gemm<EPI_RELU>,  cudaFuncAttributeMaxDynamicSharedMemorySize, SMEM_SZ);
    cudaFuncSetAttribute(mma_gemm<EPI_RESID>, cudaFuncAttributeMaxDynamicSharedMemorySize, SMEM_SZ);
    cudaFuncSetAttribute(flash_kernel,        cudaFuncAttributeMaxDynamicSharedMemorySize, FA_SMEM);

    dim3 tp(32, 8);
    transpose_qkv_kernel<<<dim3(2, 32, 16), tp>>>(Wq, wqkv);
    transpose_qkv_kernel<<<dim3(2, 32, 16), tp>>>(Wk, wqkv + (size_t)C_ * C_);
    transpose_qkv_kernel<<<dim3(2, 32, 16), tp>>>(Wv, wqkv + 2ll * C_ * C_);
    transpose_kernel<<<dim3(32, 32), tp>>>(Wproj, wpt);
    transpose_kernel<<<dim3(32, 32), tp>>>(W1, w1t);
    transpose_kernel<<<dim3(32, 32), tp>>>(W2, w2t);

    // 1. LN1
    ln_kernel<<<M_, 256>>>(x, g1, beta1, xn);
    // 2. fused QKV (N = 3072), q pre-scaled + tf32
    mma_gemm<EPI_QKV><<<dim3(3 * C_ / 128, M_ / 128), 256, SMEM_SZ>>>(xn, wqkv, nullptr, nullptr, qkv);
    // 3. fused flash attention -> g_attn
    flash_kernel<<<dim3(T_ / 128, B_ * H_), 256, FA_SMEM>>>();
    // 4. x1 = x + attn @ Wproj + bproj
    mma_gemm<EPI_PROJ><<<dim3(C_ / 128, M_ / 128), 256, SMEM_SZ>>>(attn, wpt, bproj, x, x1);
    // 5. LN2
    ln_kernel<<<M_, 256>>>(x1, g2, beta2, xn);
    // 6. h1 = relu(xn @ W1 + b1)
    mma_gemm<EPI_RELU><<<dim3(C_ / 128, M_ / 128), 256, SMEM_SZ>>>(xn, w1t, b1, nullptr, h1);
    // 7. out = x1 + h1 @ W2 + b2
    mma_gemm<EPI_RESID><<<dim3(C_ / 128, M_ / 128), 256, SMEM_SZ>>>(h1, w2t, b2, x1, out);
}

// round 6
// speedup vs baseline: 7.0226x; 1.9311x over previous
#include <cuda_runtime.h>
#include <cuda_fp16.h>
#include <math.h>
#include <cstdint>

#define B_   8
#define T_   1024
#define C_   1024
#define H_   16
#define DH   64
#define M_   (B_*T_)
#define KDIM 1024
#define EPS_ 1e-5f

// ---------------- scratch (device globals) ----------------
__device__ __half g_xnh  [M_*C_];          // LN out (fp16, GEMM A operand)
__device__ __half g_qkvh [3ll*M_*C_];      // q,k: [B,H,T,Dh]; v: [B,H,Dh,T] (transposed)
__device__ __half g_attnh[M_*C_];          // [B,T,C]
__device__ __half g_h1h  [M_*C_];          // relu(mlp1)
__device__ float  g_x1   [M_*C_];          // residual stream (fp32)
__device__ __half g_wqkvh[3ll*C_*C_];      // [N=3072][K=1024]
__device__ __half g_wpth [C_*C_];
__device__ __half g_w1th [C_*C_];
__device__ __half g_w2th [C_*C_];

// ================= helpers =================
__device__ __forceinline__ uint32_t smem_u32(const void* p) {
    uint32_t a;
    asm("{ .reg .u64 t; cvta.to.shared.u64 t, %1; cvt.u32.u64 %0, t; }" : "=r"(a) : "l"(p));
    return a;
}
__device__ __forceinline__ void cp_async16(uint32_t dst, const void* src) {
    asm volatile("cp.async.cg.shared.global [%0], [%1], 16;" :: "r"(dst), "l"(src));
}
#define CP_COMMIT() asm volatile("cp.async.commit_group;" ::: "memory")
#define CP_WAIT(n)  asm volatile("cp.async.wait_group %0;" :: "n"(n) : "memory")

// m16n8k16 fp16 MMA, fp32 accumulate
__device__ __forceinline__ void mma_f16(float* d, const uint32_t* a, const uint32_t* b) {
    asm volatile(
        "mma.sync.aligned.m16n8k16.row.col.f32.f16.f16.f32 "
        "{%0,%1,%2,%3}, {%4,%5,%6,%7}, {%8,%9}, {%0,%1,%2,%3};"
        : "+f"(d[0]), "+f"(d[1]), "+f"(d[2]), "+f"(d[3])
        : "r"(a[0]), "r"(a[1]), "r"(a[2]), "r"(a[3]), "r"(b[0]), "r"(b[1]));
}

// ================= weight transposes (fp32 -> fp16 [N][K]) ============
__global__ void __launch_bounds__(256) transpose_kernel(const float* __restrict__ in,
                                                        __half* __restrict__ out)
{
    __shared__ float tile[32][33];
    int tx = threadIdx.x, ty = threadIdx.y;
    int n0 = blockIdx.x * 32, k0 = blockIdx.y * 32;
    #pragma unroll
    for (int i = 0; i < 32; i += 8)
        tile[ty + i][tx] = in[(size_t)(k0 + ty + i) * C_ + n0 + tx];
    __syncthreads();
    #pragma unroll
    for (int i = 0; i < 32; i += 8)
        out[(size_t)(n0 + ty + i) * KDIM + k0 + tx] = __float2half_rn(tile[tx][ty + i]);
}

__global__ void __launch_bounds__(256) transpose_qkv_kernel(const float* __restrict__ in,
                                                            __half* __restrict__ out)
{
    __shared__ float tile[32][33];
    int tx = threadIdx.x, ty = threadIdx.y;
    int h = blockIdx.z;
    int d0 = blockIdx.x * 32, c0 = blockIdx.y * 32;
    #pragma unroll
    for (int i = 0; i < 32; i += 8)
        tile[ty + i][tx] = in[(size_t)h * (C_ * DH) + (size_t)(c0 + ty + i) * DH + d0 + tx];
    __syncthreads();
    #pragma unroll
    for (int i = 0; i < 32; i += 8)
        out[(size_t)(h * DH + d0 + ty + i) * KDIM + c0 + tx] = __float2half_rn(tile[tx][ty + i]);
}

// ================= fp16 mma.sync GEMM (128x128, BK=64 halves, 3-stage) ============
enum { EPI_QKV = 0, EPI_PROJ = 1, EPI_RELU = 2, EPI_RESID = 3 };

#define BKH 64
#define NCHUNK (KDIM / BKH)                // 16
#define STG_H 16384                        // halves per stage (A 8192 + B 8192)
#define SMEM_SZ (3 * STG_H * 2)            // 96KB

// swizzled half-index within a 128x64h tile: 16B group g = (k/8) XOR (row&7)
__device__ __forceinline__ int hidx(int row, int grp, int off) {
    return row * 64 + ((grp ^ (row & 7)) << 3) + off;
}

template<int EPI>
__global__ void __launch_bounds__(256) mma_gemm(
    const __half* __restrict__ A,      // [M][1024]
    const __half* __restrict__ Bt,     // [Ntot][1024]
    const float*  __restrict__ bias,
    const float*  __restrict__ resid,
    void*         __restrict__ outv)
{
    extern __shared__ __half sm[];
    int tid = threadIdx.x, wid = tid >> 5, lane = tid & 31;
    int warpM = wid & 3, warpN = wid >> 2;
    int qrow = lane >> 2, qc = lane & 3;
    int mBase = blockIdx.y * 128, nBase = blockIdx.x * 128;

    const __half* aSrc = A  + (size_t)mBase * KDIM;
    const __half* bSrc = Bt + (size_t)nBase * KDIM;

    auto load_stage = [&](int c, int s) {
        __half* dstA = sm + s * STG_H;
        __half* dstB = dstA + 8192;
        #pragma unroll
        for (int i = 0; i < 4; i++) {
            int id = tid + i * 256;
            int row = id >> 3, j = id & 7;
            cp_async16(smem_u32(dstA + hidx(row, j, 0)),
                       aSrc + (size_t)row * KDIM + c * BKH + j * 8);
            cp_async16(smem_u32(dstB + hidx(row, j, 0)),
                       bSrc + (size_t)row * KDIM + c * BKH + j * 8);
        }
    };

    float acc[2][8][4];
    #pragma unroll
    for (int mt = 0; mt < 2; mt++)
        #pragma unroll
        for (int nt = 0; nt < 8; nt++)
            #pragma unroll
            for (int r = 0; r < 4; r++) acc[mt][nt][r] = 0.f;

    load_stage(0, 0); CP_COMMIT();
    load_stage(1, 1); CP_COMMIT();

    #pragma unroll 1
    for (int c = 0; c < NCHUNK; c++) {
        if (c < NCHUNK - 2) { CP_WAIT(1); } else { CP_WAIT(0); }
        __syncthreads();
        if (c + 2 < NCHUNK) { load_stage(c + 2, (c + 2) % 3); CP_COMMIT(); }

        const __half* sA = sm + (c % 3) * STG_H;
        const __half* sB = sA + 8192;

        #pragma unroll
        for (int ks = 0; ks < 4; ks++) {
            int g0 = 2 * ks, g1 = 2 * ks + 1;
            uint32_t af[2][4];
            #pragma unroll
            for (int mt = 0; mt < 2; mt++) {
                int r0 = warpM * 32 + mt * 16 + qrow;
                af[mt][0] = *(const uint32_t*)&sA[hidx(r0,     g0, 2 * qc)];
                af[mt][1] = *(const uint32_t*)&sA[hidx(r0 + 8, g0, 2 * qc)];
                af[mt][2] = *(const uint32_t*)&sA[hidx(r0,     g1, 2 * qc)];
                af[mt][3] = *(const uint32_t*)&sA[hidx(r0 + 8, g1, 2 * qc)];
            }
            #pragma unroll
            for (int nt = 0; nt < 8; nt++) {
                int n0 = warpN * 64 + nt * 8 + qrow;
                uint32_t bf[2] = { *(const uint32_t*)&sB[hidx(n0, g0, 2 * qc)],
                                   *(const uint32_t*)&sB[hidx(n0, g1, 2 * qc)] };
                mma_f16(acc[0][nt], af[0], bf);
                mma_f16(acc[1][nt], af[1], bf);
            }
        }
    }

    // ---- epilogue ----
    #pragma unroll
    for (int mt = 0; mt < 2; mt++) {
        #pragma unroll
        for (int r = 0; r < 2; r++) {
            int m = mBase + warpM * 32 + mt * 16 + qrow + r * 8;
            #pragma unroll
            for (int nt = 0; nt < 8; nt++) {
                int col = nBase + warpN * 64 + nt * 8 + qc * 2;
                float vx = acc[mt][nt][r * 2], vy = acc[mt][nt][r * 2 + 1];
                if (EPI == EPI_QKV) {
                    __half* out = (__half*)outv;
                    int which = col >> 10, nn = col & 1023;
                    int h = nn >> 6, d = nn & 63;
                    int b = m >> 10, t = m & 1023;
                    if (which == 0) {
                        // q pre-scaled by Dh^-0.5
                        *reinterpret_cast<__half2*>(
                            &out[((size_t)(b * H_ + h) * T_ + t) * DH + d]) =
                            __floats2half2_rn(vx * 0.125f, vy * 0.125f);
                    } else if (which == 1) {
                        *reinterpret_cast<__half2*>(
                            &out[(size_t)M_ * C_ + ((size_t)(b * H_ + h) * T_ + t) * DH + d]) =
                            __floats2half2_rn(vx, vy);
                    } else {
                        // V transposed: [B,H,Dh,T] — array base offset OUTSIDE the *T_ product
                        size_t vbase = 2ll * M_ * C_;
                        size_t hd    = (size_t)(b * H_ + h) * DH;
                        out[vbase + (hd + d)     * T_ + t] = __float2half_rn(vx);
                        out[vbase + (hd + d + 1) * T_ + t] = __float2half_rn(vy);
                    }
                } else if (EPI == EPI_RELU) {
                    __half* out = (__half*)outv;
                    size_t idx = (size_t)m * C_ + col;
                    float ox = fmaxf(vx + bias[col], 0.f);
                    float oy = fmaxf(vy + bias[col + 1], 0.f);
                    *reinterpret_cast<__half2*>(&out[idx]) = __floats2half2_rn(ox, oy);
                } else {
                    float* out = (float*)outv;
                    size_t idx = (size_t)m * C_ + col;
                    float2 rs = *reinterpret_cast<const float2*>(&resid[idx]);
                    float2 o = { vx + bias[col] + rs.x, vy + bias[col + 1] + rs.y };
                    *reinterpret_cast<float2*>(&out[idx]) = o;
                }
            }
        }
    }
}

// ================= fused flash attention (fp16 mma, online softmax) ===============
// grid (8, 128): x = qt (reversed), y = bh. 256 threads, 8 warps x 16 rows.
#define FQ 0
#define FK 9216
#define FV 18432
#define FP 27136
#define FA_HALVES (27136 + 17408)
#define FA_SMEM (FA_HALVES * 2)            // 89088 bytes

__global__ void __launch_bounds__(256) flash_kernel()
{
    extern __shared__ __half fs[];
    int tid = threadIdx.x, wid = tid >> 5, lane = tid & 31;
    int qrow = lane >> 2, qc = lane & 3;
    int qt = gridDim.x - 1 - blockIdx.x;
    int bh = blockIdx.y;

    const __half* Q  = g_qkvh + ((size_t)bh * T_ + qt * 128) * DH;
    const __half* K  = g_qkvh + (size_t)M_ * C_  + (size_t)bh * T_ * DH;
    const __half* Vt = g_qkvh + 2ll * M_ * C_    + (size_t)bh * DH * T_;   // [Dh][T]

    // Q/K tiles: 128 rows x 64 halves, stride 72; V: 64 rows x 128 halves, stride 136
    auto ld_qk = [&](__half* dst, const __half* src) {
        #pragma unroll
        for (int i = 0; i < 4; i++) {
            int id = tid + i * 256;
            int row = id >> 3, j = id & 7;
            cp_async16(smem_u32(dst + row * 72 + j * 8), src + row * 64 + j * 8);
        }
    };
    auto ld_v = [&](__half* dst, const __half* src, int kt) {
        #pragma unroll
        for (int i = 0; i < 4; i++) {
            int id = tid + i * 256;
            int row = id >> 4, j = id & 15;
            cp_async16(smem_u32(dst + row * 136 + j * 8),
                       src + (size_t)row * T_ + kt * 128 + j * 8);
        }
    };

    ld_qk(fs + FQ, Q);
    CP_COMMIT();

    int rowA = wid * 16 + qrow;
    float m[2] = { -1e30f, -1e30f }, l[2] = { 0.f, 0.f };
    float o[8][4];
    #pragma unroll
    for (int nt = 0; nt < 8; nt++)
        #pragma unroll
        for (int r = 0; r < 4; r++) o[nt][r] = 0.f;

    __half* Ps = fs + FP;

    #pragma unroll 1
    for (int kt = 0; kt <= qt; kt++) {
        ld_qk(fs + FK, K + (size_t)kt * 128 * DH);
        ld_v(fs + FV, Vt, kt);
        CP_COMMIT();
        CP_WAIT(0);
        __syncthreads();

        // ---- S = Q K^T (Q pre-scaled): 16 rows x 128 cols per warp ----
        float s[16][4];
        #pragma unroll
        for (int nt = 0; nt < 16; nt++)
            #pragma unroll
            for (int r = 0; r < 4; r++) s[nt][r] = 0.f;

        #pragma unroll
        for (int ks = 0; ks < 4; ks++) {
            int k0 = ks * 16;
            uint32_t af[4] = {
                *(const uint32_t*)&fs[FQ + rowA * 72 + k0 + 2 * qc],
                *(const uint32_t*)&fs[FQ + (rowA + 8) * 72 + k0 + 2 * qc],
                *(const uint32_t*)&fs[FQ + rowA * 72 + k0 + 8 + 2 * qc],
                *(const uint32_t*)&fs[FQ + (rowA + 8) * 72 + k0 + 8 + 2 * qc] };
            #pragma unroll
            for (int nt = 0; nt < 16; nt++) {
                int n0 = nt * 8 + qrow;
                uint32_t bf[2] = {
                    *(const uint32_t*)&fs[FK + n0 * 72 + k0 + 2 * qc],
                    *(const uint32_t*)&fs[FK + n0 * 72 + k0 + 8 + 2 * qc] };
                mma_f16(s[nt], af, bf);
            }
        }

        // ---- causal mask (diagonal tile) ----
        if (kt == qt) {
            int r0 = rowA, r1 = rowA + 8;
            #pragma unroll
            for (int nt = 0; nt < 16; nt++) {
                #pragma unroll
                for (int e = 0; e < 2; e++) {
                    int col = nt * 8 + 2 * qc + e;
                    if (col > r0) s[nt][e]     = -1e30f;
                    if (col > r1) s[nt][2 + e] = -1e30f;
                }
            }
        }

        // ---- online softmax ----
        float tm0 = -1e30f, tm1 = -1e30f;
        #pragma unroll
        for (int nt = 0; nt < 16; nt++) {
            tm0 = fmaxf(tm0, fmaxf(s[nt][0], s[nt][1]));
            tm1 = fmaxf(tm1, fmaxf(s[nt][2], s[nt][3]));
        }
        tm0 = fmaxf(tm0, __shfl_xor_sync(0xffffffffu, tm0, 1));
        tm0 = fmaxf(tm0, __shfl_xor_sync(0xffffffffu, tm0, 2));
        tm1 = fmaxf(tm1, __shfl_xor_sync(0xffffffffu, tm1, 1));
        tm1 = fmaxf(tm1, __shfl_xor_sync(0xffffffffu, tm1, 2));

        float mn0 = fmaxf(m[0], tm0), mn1 = fmaxf(m[1], tm1);
        float c0 = __expf(m[0] - mn0), c1 = __expf(m[1] - mn1);
        m[0] = mn0; m[1] = mn1;

        float sum0 = 0.f, sum1 = 0.f;
        #pragma unroll
        for (int nt = 0; nt < 16; nt++) {
            float p0 = __expf(s[nt][0] - mn0);
            float p1 = __expf(s[nt][1] - mn0);
            float p2 = __expf(s[nt][2] - mn1);
            float p3 = __expf(s[nt][3] - mn1);
            sum0 += p0 + p1; sum1 += p2 + p3;
            *reinterpret_cast<__half2*>(&Ps[rowA * 136 + nt * 8 + 2 * qc]) =
                __floats2half2_rn(p0, p1);
            *reinterpret_cast<__half2*>(&Ps[(rowA + 8) * 136 + nt * 8 + 2 * qc]) =
                __floats2half2_rn(p2, p3);
        }
        sum0 += __shfl_xor_sync(0xffffffffu, sum0, 1);
        sum0 += __shfl_xor_sync(0xffffffffu, sum0, 2);
        sum1 += __shfl_xor_sync(0xffffffffu, sum1, 1);
        sum1 += __shfl_xor_sync(0xffffffffu, sum1, 2);
        l[0] = l[0] * c0 + sum0;
        l[1] = l[1] * c1 + sum1;

        #pragma unroll
        for (int nt = 0; nt < 8; nt++) {
            o[nt][0] *= c0; o[nt][1] *= c0;
            o[nt][2] *= c1; o[nt][3] *= c1;
        }
        __syncwarp();                          // P rows are warp-local

        // ---- O += P @ V : k = 128 key positions, n = 64 dims ----
        #pragma unroll
        for (int ks = 0; ks < 8; ks++) {
            int k0 = ks * 16;
            uint32_t af[4] = {
                *(const uint32_t*)&Ps[rowA * 136 + k0 + 2 * qc],
                *(const uint32_t*)&Ps[(rowA + 8) * 136 + k0 + 2 * qc],
                *(const uint32_t*)&Ps[rowA * 136 + k0 + 8 + 2 * qc],
                *(const uint32_t*)&Ps[(rowA + 8) * 136 + k0 + 8 + 2 * qc] };
            #pragma unroll
            for (int nt = 0; nt < 8; nt++) {
                int n0 = nt * 8 + qrow;
                uint32_t bf[2] = {
                    *(const uint32_t*)&fs[FV + n0 * 136 + k0 + 2 * qc],
                    *(const uint32_t*)&fs[FV + n0 * 136 + k0 + 8 + 2 * qc] };
                mma_f16(o[nt], af, bf);
            }
        }
        __syncthreads();                       // protect K/V before next cp.async
    }

    // ---- epilogue: O /= l, write fp16 [B,T,C] ----
    int b = bh >> 4, h = bh & 15;
    int t0 = qt * 128 + rowA;
    float inv0 = 1.f / l[0], inv1 = 1.f / l[1];
    #pragma unroll
    for (int nt = 0; nt < 8; nt++) {
        int col = h * 64 + nt * 8 + 2 * qc;
        *reinterpret_cast<__half2*>(&g_attnh[((size_t)(b * T_ + t0)) * C_ + col]) =
            __floats2half2_rn(o[nt][0] * inv0, o[nt][1] * inv0);
        *reinterpret_cast<__half2*>(&g_attnh[((size_t)(b * T_ + t0 + 8)) * C_ + col]) =
            __floats2half2_rn(o[nt][2] * inv1, o[nt][3] * inv1);
    }
}

// ================= LayerNorm (fp32 in -> fp16 out) =================
__global__ void __launch_bounds__(256) ln_kernel(const float* __restrict__ x,
                                                 const float* __restrict__ g,
                                                 const float* __restrict__ beta,
                                                 __half* __restrict__ out)
{
    int row = blockIdx.x, tid = threadIdx.x;
    float4 v = reinterpret_cast<const float4*>(x + (size_t)row * C_)[tid];
    float s  = v.x + v.y + v.z + v.w;
    float ss = v.x*v.x + v.y*v.y + v.z*v.z + v.w*v.w;
    __shared__ float shs[8], shss[8];
    #pragma unroll
    for (int o = 16; o; o >>= 1) {
        s  += __shfl_xor_sync(0xffffffffu, s,  o);
        ss += __shfl_xor_sync(0xffffffffu, ss, o);
    }
    if ((tid & 31) == 0) { shs[tid >> 5] = s; shss[tid >> 5] = ss; }
    __syncthreads();
    if (tid < 32) {
        float s2  = (tid < 8) ? shs[tid]  : 0.f;
        float ss2 = (tid < 8) ? shss[tid] : 0.f;
        #pragma unroll
        for (int o = 4; o; o >>= 1) {
            s2  += __shfl_xor_sync(0xffffffffu, s2,  o);
            ss2 += __shfl_xor_sync(0xffffffffu, ss2, o);
        }
        if (tid == 0) { shs[0] = s2; shss[0] = ss2; }
    }
    __syncthreads();
    float mean = shs[0] * (1.f / C_);
    float var  = shss[0] * (1.f / C_) - mean * mean;
    float inv  = rsqrtf(var + EPS_);
    float4 gg = reinterpret_cast<const float4*>(g)[tid];
    float4 bb = reinterpret_cast<const float4*>(beta)[tid];
    __half2 h0 = __floats2half2_rn(gg.x * (v.x - mean) * inv + bb.x,
                                   gg.y * (v.y - mean) * inv + bb.y);
    __half2 h1 = __floats2half2_rn(gg.z * (v.z - mean) * inv + bb.z,
                                   gg.w * (v.w - mean) * inv + bb.w);
    uint2 pk = { *(uint32_t*)&h0, *(uint32_t*)&h1 };
    reinterpret_cast<uint2*>(out + (size_t)row * C_)[tid] = pk;
}

// ================= launch =================
extern "C" void kernel_launch(void* const* d_in, const int* in_sizes, int n_in,
                              void* d_out, int out_size)
{
    const float* x     = (const float*)d_in[0];
    const float* Wq    = (const float*)d_in[1];
    const float* Wk    = (const float*)d_in[2];
    const float* Wv    = (const float*)d_in[3];
    const float* Wproj = (const float*)d_in[4];
    const float* bproj = (const float*)d_in[5];
    const float* W1    = (const float*)d_in[6];
    const float* b1    = (const float*)d_in[7];
    const float* W2    = (const float*)d_in[8];
    const float* b2    = (const float*)d_in[9];
    const float* g1    = (const float*)d_in[10];
    const float* beta1 = (const float*)d_in[11];
    const float* g2    = (const float*)d_in[12];
    const float* beta2 = (const float*)d_in[13];
    float* out = (float*)d_out;

    __half *xnh, *qkvh, *attnh, *h1h, *wqkvh, *wpth, *w1th, *w2th;
    float  *x1;
    cudaGetSymbolAddress((void**)&xnh,   g_xnh);
    cudaGetSymbolAddress((void**)&qkvh,  g_qkvh);
    cudaGetSymbolAddress((void**)&attnh, g_attnh);
    cudaGetSymbolAddress((void**)&h1h,   g_h1h);
    cudaGetSymbolAddress((void**)&x1,    g_x1);
    cudaGetSymbolAddress((void**)&wqkvh, g_wqkvh);
    cudaGetSymbolAddress((void**)&wpth,  g_wpth);
    cudaGetSymbolAddress((void**)&w1th,  g_w1th);
    cudaGetSymbolAddress((void**)&w2th,  g_w2th);

    cudaFuncSetAttribute(mma_gemm<EPI_QKV>,   cudaFuncAttributeMaxDynamicSharedMemorySize, SMEM_SZ);
    cudaFuncSetAttribute(mma_gemm<EPI_PROJ>,  cudaFuncAttributeMaxDynamicSharedMemorySize, SMEM_SZ);
    cudaFuncSetAttribute(mma_gemm<EPI_RELU>,  cudaFuncAttributeMaxDynamicSharedMemorySize, SMEM_SZ);
    cudaFuncSetAttribute(mma_gemm<EPI_RESID>, cudaFuncAttributeMaxDynamicSharedMemorySize, SMEM_SZ);
    cudaFuncSetAttribute(flash_kernel,        cudaFuncAttributeMaxDynamicSharedMemorySize, FA_SMEM);

    dim3 tp(32, 8);
    transpose_qkv_kernel<<<dim3(2, 32, 16), tp>>>(Wq, wqkvh);
    transpose_qkv_kernel<<<dim3(2, 32, 16), tp>>>(Wk, wqkvh + (size_t)C_ * C_);
    transpose_qkv_kernel<<<dim3(2, 32, 16), tp>>>(Wv, wqkvh + 2ll * C_ * C_);
    transpose_kernel<<<dim3(32, 32), tp>>>(Wproj, wpth);
    transpose_kernel<<<dim3(32, 32), tp>>>(W1, w1th);
    transpose_kernel<<<dim3(32, 32), tp>>>(W2, w2th);

    // 1. LN1 -> fp16
    ln_kernel<<<M_, 256>>>(x, g1, beta1, xnh);
    // 2. fused QKV (N = 3072); q scaled; V written transposed
    mma_gemm<EPI_QKV><<<dim3(3 * C_ / 128, M_ / 128), 256, SMEM_SZ>>>(xnh, wqkvh, nullptr, nullptr, qkvh);
    // 3. fused flash attention -> g_attnh
    flash_kernel<<<dim3(T_ / 128, B_ * H_), 256, FA_SMEM>>>();
    // 4. x1 = x + attn @ Wproj + bproj (fp32)
    mma_gemm<EPI_PROJ><<<dim3(C_ / 128, M_ / 128), 256, SMEM_SZ>>>(attnh, wpth, bproj, x, x1);
    // 5. LN2 -> fp16
    ln_kernel<<<M_, 256>>>(x1, g2, beta2, xnh);
    // 6. h1 = relu(xn @ W1 + b1) -> fp16
    mma_gemm<EPI_RELU><<<dim3(C_ / 128, M_ / 128), 256, SMEM_SZ>>>(xnh, w1th, b1, nullptr, h1h);
    // 7. out = x1 + h1 @ W2 + b2 (fp32)
    mma_gemm<EPI_RESID><<<dim3(C_ / 128, M_ / 128), 256, SMEM_SZ>>>(h1h, w2th, b2, x1, out);
}